// round 5
// baseline (speedup 1.0000x reference)
#include <cuda_runtime.h>

#define NSAMPLE 32
#define MAXN 4096
#define FULL 0xffffffffu

// scratch (no allocation allowed)
__device__ int g_cnt[MAXN];
__device__ int g_off[MAXN];
__device__ int g_total;
__device__ int g_ball[MAXN * NSAMPLE];
__device__ int g_arrive;   // zero-init; reset by last block each launch

// ---------------------------------------------------------------------------
// Fused query + scan (unchanged from passing R4 kernel)
// ---------------------------------------------------------------------------
template<int NCH>
__global__ void query_scan_kernel(const float* __restrict__ xyz,
                                  const float* __restrict__ new_xyz,
                                  const float* __restrict__ rois,
                                  int N, int Nb, int M, int K, int BM,
                                  int nblocks) {
    __shared__ float s_cx[1024], s_cy[1024], s_cz[1024], s_r2[1024];
    int tid = threadIdx.x;
    int lane = tid & 31;

    for (int e = tid; e < BM; e += blockDim.x) {
        const float* ro = rois + (size_t)e * 7;
        s_cx[e] = ro[0]; s_cy[e] = ro[1]; s_cz[e] = ro[2];
        s_r2[e] = __fadd_rn(__fadd_rn(__fmul_rn(ro[3], ro[3]),
                                      __fmul_rn(ro[4], ro[4])),
                            __fmul_rn(ro[5], ro[5]));
    }
    __syncthreads();

    int i = blockIdx.x * (blockDim.x >> 5) + (tid >> 5);
    if (i < N) {
        float px = xyz[3 * i + 0];
        float py = xyz[3 * i + 1];
        float pz = xyz[3 * i + 2];
        int b = i / Nb;
        int MK = M * K;
        const float* gridb = new_xyz + (size_t)b * MK * 3;
        int rbase = b * M;

        int cnt = 0;
        int ngroups = (M + 31) >> 5;
        for (int g = 0; g < ngroups && cnt < NSAMPLE; ++g) {
            int r = (g << 5) + lane;
            bool ib = false;
            if (r < M) {
                int e = rbase + r;
                float dx = px - s_cx[e], dy = py - s_cy[e], dz = pz - s_cz[e];
                float d2b = __fadd_rn(__fadd_rn(__fmul_rn(dx, dx), __fmul_rn(dy, dy)), __fmul_rn(dz, dz));
                ib = (d2b <= s_r2[e]);
            }
            unsigned rm = __ballot_sync(FULL, ib);
            while (rm && cnt < NSAMPLE) {
                int rb = __ffs(rm) - 1;
                rm &= rm - 1;
                int roi = (g << 5) + rb;
                int basej = roi * K;

                float d2s[NCH];
#pragma unroll
                for (int c = 0; c < NCH; ++c) {
                    int jl = (c << 5) + lane;
                    d2s[c] = 4.0f;
                    if (jl < K) {
                        const float* gp = gridb + (size_t)(basej + jl) * 3;
                        float dx = px - gp[0], dy = py - gp[1], dz = pz - gp[2];
                        d2s[c] = __fadd_rn(__fadd_rn(__fmul_rn(dx, dx), __fmul_rn(dy, dy)), __fmul_rn(dz, dz));
                    }
                }
                unsigned masks[NCH];
#pragma unroll
                for (int c = 0; c < NCH; ++c)
                    masks[c] = __ballot_sync(FULL, d2s[c] <= 1.0f);
#pragma unroll
                for (int c = 0; c < NCH; ++c) {
                    if (cnt < NSAMPLE) {
                        unsigned m = masks[c];
                        int rank = cnt + __popc(m & ((1u << lane) - 1u));
                        if (((m >> lane) & 1u) && rank < NSAMPLE)
                            g_ball[i * NSAMPLE + rank] = b * MK + basej + (c << 5) + lane;
                        cnt += __popc(m);
                    }
                }
            }
        }
        if (lane == 0) g_cnt[i] = cnt < NSAMPLE ? cnt : NSAMPLE;
    }

    // ---- last-block fused scan ----
    __threadfence();
    __syncthreads();
    __shared__ int s_last;
    if (tid == 0) s_last = (atomicAdd(&g_arrive, 1) == nblocks - 1) ? 1 : 0;
    __syncthreads();
    if (s_last) {
        __shared__ int wsum[8];
        const int PER = MAXN / 256;
        int wid = tid >> 5;
        int base = tid * PER;
        int vals[PER];
        int tot = 0;
#pragma unroll
        for (int k = 0; k < PER; ++k) {
            int idx = base + k;
            int v = (idx < N) ? __ldcg(&g_cnt[idx]) : 0;
            vals[k] = v;
            tot += v;
        }
        int inc = tot;
#pragma unroll
        for (int d = 1; d < 32; d <<= 1) {
            int y = __shfl_up_sync(FULL, inc, d);
            if (lane >= d) inc += y;
        }
        if (lane == 31) wsum[wid] = inc;
        __syncthreads();
        int wpre = 0;
#pragma unroll
        for (int w = 0; w < 8; ++w)
            if (w < wid) wpre += wsum[w];
        int run = wpre + inc - tot;
#pragma unroll
        for (int k = 0; k < PER; ++k) {
            int idx = base + k;
            if (idx < N) g_off[idx] = run;
            run += vals[k];
        }
        if (tid == 255) g_total = wpre + inc;
        __syncthreads();
        if (tid == 0) g_arrive = 0;
    }
}

// ---------------------------------------------------------------------------
// Fallback generic query + scan (for unexpected shapes)
// ---------------------------------------------------------------------------
__global__ void query_kernel_generic(const float* __restrict__ xyz,
                                     const float* __restrict__ new_xyz,
                                     const float* __restrict__ rois,
                                     int N, int Nb, int M, int K) {
    int warp = (blockIdx.x * blockDim.x + threadIdx.x) >> 5;
    int lane = threadIdx.x & 31;
    if (warp >= N) return;
    int i = warp;
    float px = xyz[3 * i + 0], py = xyz[3 * i + 1], pz = xyz[3 * i + 2];
    int b = i / Nb;
    int MK = M * K;
    const float* roib  = rois    + (size_t)b * M * 7;
    const float* gridb = new_xyz + (size_t)b * MK * 3;
    int cnt = 0;
    int ngroups = (M + 31) >> 5;
    for (int g = 0; g < ngroups && cnt < NSAMPLE; ++g) {
        int r = (g << 5) + lane;
        bool ib = false;
        if (r < M) {
            const float* ro = roib + (size_t)r * 7;
            float dx = px - ro[0], dy = py - ro[1], dz = pz - ro[2];
            float d2b = __fadd_rn(__fadd_rn(__fmul_rn(dx, dx), __fmul_rn(dy, dy)), __fmul_rn(dz, dz));
            float r2  = __fadd_rn(__fadd_rn(__fmul_rn(ro[3], ro[3]), __fmul_rn(ro[4], ro[4])), __fmul_rn(ro[5], ro[5]));
            ib = (d2b <= r2);
        }
        unsigned rm = __ballot_sync(FULL, ib);
        while (rm && cnt < NSAMPLE) {
            int rb = __ffs(rm) - 1;
            rm &= rm - 1;
            int basej = ((g << 5) + rb) * K;
            int nchunks = (K + 31) >> 5;
            for (int c = 0; c < nchunks && cnt < NSAMPLE; ++c) {
                int jl = (c << 5) + lane;
                bool ok = false;
                if (jl < K) {
                    const float* gp = gridb + (size_t)(basej + jl) * 3;
                    float dx = px - gp[0], dy = py - gp[1], dz = pz - gp[2];
                    float d2 = __fadd_rn(__fadd_rn(__fmul_rn(dx, dx), __fmul_rn(dy, dy)), __fmul_rn(dz, dz));
                    ok = (d2 <= 1.0f);
                }
                unsigned m = __ballot_sync(FULL, ok);
                int rank = cnt + __popc(m & ((1u << lane) - 1u));
                if (ok && rank < NSAMPLE)
                    g_ball[i * NSAMPLE + rank] = b * MK + basej + jl;
                cnt += __popc(m);
            }
        }
    }
    if (lane == 0) g_cnt[i] = cnt < NSAMPLE ? cnt : NSAMPLE;
}

__global__ void scan_kernel_generic(int N) {
    __shared__ int wsum[4];
    int t = threadIdx.x, lane = t & 31, wid = t >> 5;
    const int PER = MAXN / 128;
    int base = t * PER;
    int vals[PER]; int tot = 0;
#pragma unroll
    for (int k = 0; k < PER; ++k) {
        int idx = base + k;
        int v = (idx < N) ? g_cnt[idx] : 0;
        vals[k] = v; tot += v;
    }
    int inc = tot;
#pragma unroll
    for (int d = 1; d < 32; d <<= 1) {
        int y = __shfl_up_sync(FULL, inc, d);
        if (lane >= d) inc += y;
    }
    if (lane == 31) wsum[wid] = inc;
    __syncthreads();
    int wpre = 0;
#pragma unroll
    for (int w = 0; w < 4; ++w) if (w < wid) wpre += wsum[w];
    int run = wpre + inc - tot;
#pragma unroll
    for (int k = 0; k < PER; ++k) {
        int idx = base + k;
        if (idx < N) g_off[idx] = run;
        run += vals[k];
    }
    if (t == 127) g_total = wpre + inc;
}

// ---------------------------------------------------------------------------
// Scatter: block-per-point, warp-per-row, hoisted invariants; + tail zero
// ---------------------------------------------------------------------------
#define SCT_THREADS 128
#define ZBLK 1024

__global__ void scatter_kernel(const float* __restrict__ xyz,
                               const float* __restrict__ new_xyz_flat,
                               const float* __restrict__ feat,
                               float* __restrict__ out_gf,
                               float* __restrict__ out_idx,
                               int N, int C, int L) {
    int blk = blockIdx.x;
    int t = threadIdx.x;
    int D = 3 + C;   // D <= 96 supported

    if (blk < N) {
        __shared__ int   sball[NSAMPLE];
        __shared__ float sval[99];   // [0..2]=xyz, [3..3+C)
        int i = blk;
        int cnt = g_cnt[i];
        if (cnt == 0) return;
        int off = g_off[i];

        if (t < cnt) sball[t] = g_ball[i * NSAMPLE + t];
        if (t < 3)   sval[t] = xyz[3 * i + t];
        if (t < C)   sval[3 + t] = feat[(size_t)i * C + t];
        __syncthreads();

        int wid = t >> 5;
        int lane = t & 31;
        // hoist per-lane row values (loop invariant)
        float v1 = (lane      < D) ? sval[lane]      : 0.f;
        float v2 = (32 + lane < D) ? sval[32 + lane] : 0.f;
        float v3 = (64 + lane < D) ? sval[64 + lane] : 0.f;
        bool w2 = (32 + lane < D);
        bool w3 = (64 + lane < D);

        float* dst = out_gf + (size_t)off * D;
        for (int s = wid; s < cnt; s += (SCT_THREADS >> 5)) {
            int idx = sball[s];
            float* row = dst + s * D;
            float v = v1;
            if (lane < 3)
                v = v1 - __ldg(&new_xyz_flat[(size_t)idx * 3 + lane]);
            if (lane < D) row[lane] = v;
            if (w2) row[32 + lane] = v2;
            if (w3) row[64 + lane] = v3;
        }
        if (t < cnt) out_idx[off + t] = (float)sball[t];
    } else {
        int zb = blk - N;
        int nind = g_total;
        long S = (long)nind * D;
        long E = (long)L * D;
        long gt = (long)zb * SCT_THREADS + t;
        long TOT = (long)ZBLK * SCT_THREADS;
        long S4 = (S + 3) & ~3L;
        if (S4 > E) S4 = E;
        if (gt < (S4 - S)) out_gf[S + gt] = 0.f;
        float4 z4 = make_float4(0.f, 0.f, 0.f, 0.f);
        long n4 = (E - S4) >> 2;
        float4* p4 = (float4*)(out_gf + S4);
        for (long q = gt; q < n4; q += TOT) p4[q] = z4;
        long rem = (E - S4) & 3L;
        if (gt < rem) out_gf[S4 + (n4 << 2) + gt] = 0.f;
        for (long q = nind + gt; q < L; q += TOT) out_idx[q] = 0.f;
    }
}

// ---------------------------------------------------------------------------
extern "C" void kernel_launch(void* const* d_in, const int* in_sizes, int n_in,
                              void* d_out, int out_size) {
    const float* xyz     = (const float*)d_in[0];
    const float* new_xyz = (const float*)d_in[2];
    const float* rois    = (const float*)d_in[3];
    const float* feats   = (const float*)d_in[4];

    int N  = in_sizes[0] / 3;
    int B  = in_sizes[1];
    int Nb = N / B;
    int M  = in_sizes[3] / (B * 7);
    int K  = in_sizes[2] / (B * M * 3);
    int C  = in_sizes[4] / N;
    int L  = N * NSAMPLE;
    int D  = 3 + C;
    int BM = B * M;

    int nthreads = N * 32;
    int nblocks = (nthreads + 255) / 256;
    int nch = (K + 31) / 32;

    bool fused = (BM <= 1024) && (N <= MAXN) && (nch >= 1) && (nch <= 8);
    if (fused) {
        switch (nch) {
        case 1: query_scan_kernel<1><<<nblocks, 256>>>(xyz, new_xyz, rois, N, Nb, M, K, BM, nblocks); break;
        case 2: query_scan_kernel<2><<<nblocks, 256>>>(xyz, new_xyz, rois, N, Nb, M, K, BM, nblocks); break;
        case 3: query_scan_kernel<3><<<nblocks, 256>>>(xyz, new_xyz, rois, N, Nb, M, K, BM, nblocks); break;
        case 4: query_scan_kernel<4><<<nblocks, 256>>>(xyz, new_xyz, rois, N, Nb, M, K, BM, nblocks); break;
        case 5: query_scan_kernel<5><<<nblocks, 256>>>(xyz, new_xyz, rois, N, Nb, M, K, BM, nblocks); break;
        case 6: query_scan_kernel<6><<<nblocks, 256>>>(xyz, new_xyz, rois, N, Nb, M, K, BM, nblocks); break;
        case 7: query_scan_kernel<7><<<nblocks, 256>>>(xyz, new_xyz, rois, N, Nb, M, K, BM, nblocks); break;
        default: query_scan_kernel<8><<<nblocks, 256>>>(xyz, new_xyz, rois, N, Nb, M, K, BM, nblocks); break;
        }
    } else {
        query_kernel_generic<<<nblocks, 256>>>(xyz, new_xyz, rois, N, Nb, M, K);
        scan_kernel_generic<<<1, 128>>>(N);
    }

    scatter_kernel<<<N + ZBLK, SCT_THREADS>>>(
        xyz, new_xyz, feats,
        (float*)d_out, (float*)d_out + (size_t)L * D, N, C, L);
}

// round 10
// speedup vs baseline: 1.4587x; 1.4587x over previous
#include <cuda_runtime.h>

#define NSAMPLE 32
#define MAXN 4096
#define FULL 0xffffffffu
#define MAXD 99

// scratch (no allocation allowed)
__device__ int g_cnt[MAXN];
__device__ int g_off[MAXN];
__device__ int g_total;
__device__ int g_ball[MAXN * NSAMPLE];
__device__ int g_arrive;   // zero-init; reset by last block each launch

// ---------------------------------------------------------------------------
// Fused query + scan (byte-identical to the passing R4 kernel)
// ---------------------------------------------------------------------------
template<int NCH>
__global__ void query_scan_kernel(const float* __restrict__ xyz,
                                  const float* __restrict__ new_xyz,
                                  const float* __restrict__ rois,
                                  int N, int Nb, int M, int K, int BM,
                                  int nblocks) {
    __shared__ float s_cx[1024], s_cy[1024], s_cz[1024], s_r2[1024];
    int tid = threadIdx.x;
    int lane = tid & 31;

    for (int e = tid; e < BM; e += blockDim.x) {
        const float* ro = rois + (size_t)e * 7;
        s_cx[e] = ro[0]; s_cy[e] = ro[1]; s_cz[e] = ro[2];
        s_r2[e] = __fadd_rn(__fadd_rn(__fmul_rn(ro[3], ro[3]),
                                      __fmul_rn(ro[4], ro[4])),
                            __fmul_rn(ro[5], ro[5]));
    }
    __syncthreads();

    int i = blockIdx.x * (blockDim.x >> 5) + (tid >> 5);
    if (i < N) {
        float px = xyz[3 * i + 0];
        float py = xyz[3 * i + 1];
        float pz = xyz[3 * i + 2];
        int b = i / Nb;
        int MK = M * K;
        const float* gridb = new_xyz + (size_t)b * MK * 3;
        int rbase = b * M;

        int cnt = 0;
        int ngroups = (M + 31) >> 5;
        for (int g = 0; g < ngroups && cnt < NSAMPLE; ++g) {
            int r = (g << 5) + lane;
            bool ib = false;
            if (r < M) {
                int e = rbase + r;
                float dx = px - s_cx[e], dy = py - s_cy[e], dz = pz - s_cz[e];
                float d2b = __fadd_rn(__fadd_rn(__fmul_rn(dx, dx), __fmul_rn(dy, dy)), __fmul_rn(dz, dz));
                ib = (d2b <= s_r2[e]);
            }
            unsigned rm = __ballot_sync(FULL, ib);
            while (rm && cnt < NSAMPLE) {
                int rb = __ffs(rm) - 1;
                rm &= rm - 1;
                int roi = (g << 5) + rb;
                int basej = roi * K;

                float d2s[NCH];
#pragma unroll
                for (int c = 0; c < NCH; ++c) {
                    int jl = (c << 5) + lane;
                    d2s[c] = 4.0f;
                    if (jl < K) {
                        const float* gp = gridb + (size_t)(basej + jl) * 3;
                        float dx = px - gp[0], dy = py - gp[1], dz = pz - gp[2];
                        d2s[c] = __fadd_rn(__fadd_rn(__fmul_rn(dx, dx), __fmul_rn(dy, dy)), __fmul_rn(dz, dz));
                    }
                }
                unsigned masks[NCH];
#pragma unroll
                for (int c = 0; c < NCH; ++c)
                    masks[c] = __ballot_sync(FULL, d2s[c] <= 1.0f);
#pragma unroll
                for (int c = 0; c < NCH; ++c) {
                    if (cnt < NSAMPLE) {
                        unsigned m = masks[c];
                        int rank = cnt + __popc(m & ((1u << lane) - 1u));
                        if (((m >> lane) & 1u) && rank < NSAMPLE)
                            g_ball[i * NSAMPLE + rank] = b * MK + basej + (c << 5) + lane;
                        cnt += __popc(m);
                    }
                }
            }
        }
        if (lane == 0) g_cnt[i] = cnt < NSAMPLE ? cnt : NSAMPLE;
    }

    // ---- last-block fused scan ----
    __threadfence();
    __syncthreads();
    __shared__ int s_last;
    if (tid == 0) s_last = (atomicAdd(&g_arrive, 1) == nblocks - 1) ? 1 : 0;
    __syncthreads();
    if (s_last) {
        __shared__ int wsum[8];
        const int PER = MAXN / 256;
        int wid = tid >> 5;
        int base = tid * PER;
        int vals[PER];
        int tot = 0;
#pragma unroll
        for (int k = 0; k < PER; ++k) {
            int idx = base + k;
            int v = (idx < N) ? __ldcg(&g_cnt[idx]) : 0;
            vals[k] = v;
            tot += v;
        }
        int inc = tot;
#pragma unroll
        for (int d = 1; d < 32; d <<= 1) {
            int y = __shfl_up_sync(FULL, inc, d);
            if (lane >= d) inc += y;
        }
        if (lane == 31) wsum[wid] = inc;
        __syncthreads();
        int wpre = 0;
#pragma unroll
        for (int w = 0; w < 8; ++w)
            if (w < wid) wpre += wsum[w];
        int run = wpre + inc - tot;
#pragma unroll
        for (int k = 0; k < PER; ++k) {
            int idx = base + k;
            if (idx < N) g_off[idx] = run;
            run += vals[k];
        }
        if (tid == 255) g_total = wpre + inc;
        __syncthreads();
        if (tid == 0) g_arrive = 0;
    }
}

// ---------------------------------------------------------------------------
// Fallback generic query + scan (for unexpected shapes)
// ---------------------------------------------------------------------------
__global__ void query_kernel_generic(const float* __restrict__ xyz,
                                     const float* __restrict__ new_xyz,
                                     const float* __restrict__ rois,
                                     int N, int Nb, int M, int K) {
    int warp = (blockIdx.x * blockDim.x + threadIdx.x) >> 5;
    int lane = threadIdx.x & 31;
    if (warp >= N) return;
    int i = warp;
    float px = xyz[3 * i + 0], py = xyz[3 * i + 1], pz = xyz[3 * i + 2];
    int b = i / Nb;
    int MK = M * K;
    const float* roib  = rois    + (size_t)b * M * 7;
    const float* gridb = new_xyz + (size_t)b * MK * 3;
    int cnt = 0;
    int ngroups = (M + 31) >> 5;
    for (int g = 0; g < ngroups && cnt < NSAMPLE; ++g) {
        int r = (g << 5) + lane;
        bool ib = false;
        if (r < M) {
            const float* ro = roib + (size_t)r * 7;
            float dx = px - ro[0], dy = py - ro[1], dz = pz - ro[2];
            float d2b = __fadd_rn(__fadd_rn(__fmul_rn(dx, dx), __fmul_rn(dy, dy)), __fmul_rn(dz, dz));
            float r2  = __fadd_rn(__fadd_rn(__fmul_rn(ro[3], ro[3]), __fmul_rn(ro[4], ro[4])), __fmul_rn(ro[5], ro[5]));
            ib = (d2b <= r2);
        }
        unsigned rm = __ballot_sync(FULL, ib);
        while (rm && cnt < NSAMPLE) {
            int rb = __ffs(rm) - 1;
            rm &= rm - 1;
            int basej = ((g << 5) + rb) * K;
            int nchunks = (K + 31) >> 5;
            for (int c = 0; c < nchunks && cnt < NSAMPLE; ++c) {
                int jl = (c << 5) + lane;
                bool ok = false;
                if (jl < K) {
                    const float* gp = gridb + (size_t)(basej + jl) * 3;
                    float dx = px - gp[0], dy = py - gp[1], dz = pz - gp[2];
                    float d2 = __fadd_rn(__fadd_rn(__fmul_rn(dx, dx), __fmul_rn(dy, dy)), __fmul_rn(dz, dz));
                    ok = (d2 <= 1.0f);
                }
                unsigned m = __ballot_sync(FULL, ok);
                int rank = cnt + __popc(m & ((1u << lane) - 1u));
                if (ok && rank < NSAMPLE)
                    g_ball[i * NSAMPLE + rank] = b * MK + basej + jl;
                cnt += __popc(m);
            }
        }
    }
    if (lane == 0) g_cnt[i] = cnt < NSAMPLE ? cnt : NSAMPLE;
}

__global__ void scan_kernel_generic(int N) {
    __shared__ int wsum[4];
    int t = threadIdx.x, lane = t & 31, wid = t >> 5;
    const int PER = MAXN / 128;
    int base = t * PER;
    int vals[PER]; int tot = 0;
#pragma unroll
    for (int k = 0; k < PER; ++k) {
        int idx = base + k;
        int v = (idx < N) ? g_cnt[idx] : 0;
        vals[k] = v; tot += v;
    }
    int inc = tot;
#pragma unroll
    for (int d = 1; d < 32; d <<= 1) {
        int y = __shfl_up_sync(FULL, inc, d);
        if (lane >= d) inc += y;
    }
    if (lane == 31) wsum[wid] = inc;
    __syncthreads();
    int wpre = 0;
#pragma unroll
    for (int w = 0; w < 4; ++w) if (w < wid) wpre += wsum[w];
    int run = wpre + inc - tot;
#pragma unroll
    for (int k = 0; k < PER; ++k) {
        int idx = base + k;
        if (idx < N) g_off[idx] = run;
        run += vals[k];
    }
    if (t == 127) g_total = wpre + inc;
}

// ---------------------------------------------------------------------------
// Scatter: block-per-point; build rows in smem, flush flat with float4
// ---------------------------------------------------------------------------
#define SCT_THREADS 128
#define ZBLK 1024

__global__ void scatter_kernel(const float* __restrict__ xyz,
                               const float* __restrict__ new_xyz_flat,
                               const float* __restrict__ feat,
                               float* __restrict__ out_gf,
                               float* __restrict__ out_idx,
                               int N, int C, int L) {
    int blk = blockIdx.x;
    int t = threadIdx.x;
    int D = 3 + C;   // D <= MAXD

    if (blk < N) {
        __shared__ int   sball[NSAMPLE];
        __shared__ float sval[MAXD];
        __shared__ float srow[NSAMPLE * MAXD];
        int i = blk;
        int cnt = g_cnt[i];
        if (cnt == 0) return;
        int off = g_off[i];

        if (t < cnt) sball[t] = g_ball[i * NSAMPLE + t];
        if (t < 3)   sval[t] = xyz[3 * i + t];
        if (t < C)   sval[3 + t] = feat[(size_t)i * C + t];
        __syncthreads();

        int wid = t >> 5;
        int lane = t & 31;
        float v1 = (lane      < D) ? sval[lane]      : 0.f;
        float v2 = (32 + lane < D) ? sval[32 + lane] : 0.f;
        float v3 = (64 + lane < D) ? sval[64 + lane] : 0.f;
        bool w2 = (32 + lane < D);
        bool w3 = (64 + lane < D);

        // phase 1: build rows in shared (smem tolerates the strided pattern)
        for (int s = wid; s < cnt; s += (SCT_THREADS >> 5)) {
            int idx = sball[s];
            float* row = srow + s * D;
            float v = v1;
            if (lane < 3)
                v = v1 - __ldg(&new_xyz_flat[(size_t)idx * 3 + lane]);
            if (lane < D) row[lane] = v;
            if (w2) row[32 + lane] = v2;
            if (w3) row[64 + lane] = v3;
        }
        if (t < cnt) out_idx[off + t] = (float)sball[t];
        __syncthreads();

        // phase 2: flat coalesced flush, float4 body
        int total = cnt * D;
        float* dst = out_gf + (size_t)off * D;
        int nhead = (4 - (int)(((size_t)off * D) & 3)) & 3;
        if (nhead > total) nhead = total;
        if (t < nhead) dst[t] = srow[t];
        int n4 = (total - nhead) >> 2;
        float4* d4 = (float4*)(dst + nhead);
        const float* sp0 = srow + nhead;
        for (int q = t; q < n4; q += SCT_THREADS) {
            const float* sp = sp0 + (q << 2);
            d4[q] = make_float4(sp[0], sp[1], sp[2], sp[3]);
        }
        int done = nhead + (n4 << 2);
        int rem = total - done;
        if (t < rem) dst[done + t] = srow[done + t];
    } else {
        int zb = blk - N;
        int nind = g_total;
        long S = (long)nind * D;
        long E = (long)L * D;
        long gt = (long)zb * SCT_THREADS + t;
        long TOT = (long)ZBLK * SCT_THREADS;
        long S4 = (S + 3) & ~3L;
        if (S4 > E) S4 = E;
        if (gt < (S4 - S)) out_gf[S + gt] = 0.f;
        float4 z4 = make_float4(0.f, 0.f, 0.f, 0.f);
        long n4 = (E - S4) >> 2;
        float4* p4 = (float4*)(out_gf + S4);
        for (long q = gt; q < n4; q += TOT) p4[q] = z4;
        long rem = (E - S4) & 3L;
        if (gt < rem) out_gf[S4 + (n4 << 2) + gt] = 0.f;
        for (long q = nind + gt; q < L; q += TOT) out_idx[q] = 0.f;
    }
}

// ---------------------------------------------------------------------------
extern "C" void kernel_launch(void* const* d_in, const int* in_sizes, int n_in,
                              void* d_out, int out_size) {
    const float* xyz     = (const float*)d_in[0];
    const float* new_xyz = (const float*)d_in[2];
    const float* rois    = (const float*)d_in[3];
    const float* feats   = (const float*)d_in[4];

    int N  = in_sizes[0] / 3;
    int B  = in_sizes[1];
    int Nb = N / B;
    int M  = in_sizes[3] / (B * 7);
    int K  = in_sizes[2] / (B * M * 3);
    int C  = in_sizes[4] / N;
    int L  = N * NSAMPLE;
    int D  = 3 + C;
    int BM = B * M;

    int nthreads = N * 32;
    int nblocks = (nthreads + 255) / 256;
    int nch = (K + 31) / 32;

    bool fused = (BM <= 1024) && (N <= MAXN) && (nch >= 1) && (nch <= 8);
    if (fused) {
        switch (nch) {
        case 1: query_scan_kernel<1><<<nblocks, 256>>>(xyz, new_xyz, rois, N, Nb, M, K, BM, nblocks); break;
        case 2: query_scan_kernel<2><<<nblocks, 256>>>(xyz, new_xyz, rois, N, Nb, M, K, BM, nblocks); break;
        case 3: query_scan_kernel<3><<<nblocks, 256>>>(xyz, new_xyz, rois, N, Nb, M, K, BM, nblocks); break;
        case 4: query_scan_kernel<4><<<nblocks, 256>>>(xyz, new_xyz, rois, N, Nb, M, K, BM, nblocks); break;
        case 5: query_scan_kernel<5><<<nblocks, 256>>>(xyz, new_xyz, rois, N, Nb, M, K, BM, nblocks); break;
        case 6: query_scan_kernel<6><<<nblocks, 256>>>(xyz, new_xyz, rois, N, Nb, M, K, BM, nblocks); break;
        case 7: query_scan_kernel<7><<<nblocks, 256>>>(xyz, new_xyz, rois, N, Nb, M, K, BM, nblocks); break;
        default: query_scan_kernel<8><<<nblocks, 256>>>(xyz, new_xyz, rois, N, Nb, M, K, BM, nblocks); break;
        }
    } else {
        query_kernel_generic<<<nblocks, 256>>>(xyz, new_xyz, rois, N, Nb, M, K);
        scan_kernel_generic<<<1, 128>>>(N);
    }

    scatter_kernel<<<N + ZBLK, SCT_THREADS>>>(
        xyz, new_xyz, feats,
        (float*)d_out, (float*)d_out + (size_t)L * D, N, C, L);
}

// round 12
// speedup vs baseline: 1.7204x; 1.1794x over previous
#include <cuda_runtime.h>

#define NSAMPLE 32
#define MAXN 4096
#define FULL 0xffffffffu
#define MAXDF 40   // fused path supports D = 3+C <= 40

// scratch (no allocation allowed; zero-initialized)
__device__ int g_cnt[MAXN];
__device__ int g_off[MAXN];
__device__ int g_total;
__device__ int g_ball[MAXN * NSAMPLE];
__device__ int g_arrive;
__device__ int g_arrive2;
__device__ int g_flag;

// ---------------------------------------------------------------------------
// Fully fused: zero + query + scan (grid barrier) + scatter. Single launch.
// Query comparisons byte-identical to the passing R4 kernel.
// Requires: all blocks resident (guaranteed by __launch_bounds__(256,4) and
// nblocks <= 4*148), BM<=1024, D<=MAXDF, N<=MAXN.
// ---------------------------------------------------------------------------
template<int NCH>
__global__ void __launch_bounds__(256, 4)
fused_kernel(const float* __restrict__ xyz,
             const float* __restrict__ new_xyz,
             const float* __restrict__ rois,
             const float* __restrict__ feat,
             float* __restrict__ out,
             int N, int Nb, int M, int K, int C, int L,
             int BM, int out_size) {
    // sbuf layout: phase1: cx[1024] cy[1024] cz[1024] r2[1024]
    //              phase2: srow 8*1280 floats + sval 8*40 floats
    __shared__ float sbuf[10560];
    __shared__ int s_last;
    __shared__ int wsum[8];

    int tid = threadIdx.x;
    int lane = tid & 31;
    int wid = tid >> 5;
    int blk = blockIdx.x;
    int nblocks = gridDim.x;
    int D = 3 + C;

    // ---- phase 0: zero the whole output (overlaps with query latency) ----
    {
        int total4 = out_size >> 2;
        float4 z = make_float4(0.f, 0.f, 0.f, 0.f);
        float4* o4 = (float4*)out;
        for (int q = blk * 256 + tid; q < total4; q += nblocks * 256) o4[q] = z;
        int rem = out_size & 3;
        if (blk == 0 && tid < rem) out[(size_t)total4 * 4 + tid] = 0.f;
    }

    // ---- phase 1: RoIs to smem + ball query (exact R4 math) ----
    float* s_cx = sbuf;
    float* s_cy = sbuf + 1024;
    float* s_cz = sbuf + 2048;
    float* s_r2 = sbuf + 3072;
    for (int e = tid; e < BM; e += 256) {
        const float* ro = rois + (size_t)e * 7;
        s_cx[e] = ro[0]; s_cy[e] = ro[1]; s_cz[e] = ro[2];
        s_r2[e] = __fadd_rn(__fadd_rn(__fmul_rn(ro[3], ro[3]),
                                      __fmul_rn(ro[4], ro[4])),
                            __fmul_rn(ro[5], ro[5]));
    }
    __syncthreads();

    int i = blk * 8 + wid;
    int cnt = 0;
    float px = 0.f, py = 0.f, pz = 0.f;
    if (i < N) {
        px = xyz[3 * i + 0];
        py = xyz[3 * i + 1];
        pz = xyz[3 * i + 2];
        int b = i / Nb;
        int MK = M * K;
        const float* gridb = new_xyz + (size_t)b * MK * 3;
        int rbase = b * M;

        int ngroups = (M + 31) >> 5;
        for (int g = 0; g < ngroups && cnt < NSAMPLE; ++g) {
            int r = (g << 5) + lane;
            bool ib = false;
            if (r < M) {
                int e = rbase + r;
                float dx = px - s_cx[e], dy = py - s_cy[e], dz = pz - s_cz[e];
                float d2b = __fadd_rn(__fadd_rn(__fmul_rn(dx, dx), __fmul_rn(dy, dy)), __fmul_rn(dz, dz));
                ib = (d2b <= s_r2[e]);
            }
            unsigned rm = __ballot_sync(FULL, ib);
            while (rm && cnt < NSAMPLE) {
                int rb = __ffs(rm) - 1;
                rm &= rm - 1;
                int roi = (g << 5) + rb;
                int basej = roi * K;

                float d2s[NCH];
#pragma unroll
                for (int c = 0; c < NCH; ++c) {
                    int jl = (c << 5) + lane;
                    d2s[c] = 4.0f;
                    if (jl < K) {
                        const float* gp = gridb + (size_t)(basej + jl) * 3;
                        float dx = px - gp[0], dy = py - gp[1], dz = pz - gp[2];
                        d2s[c] = __fadd_rn(__fadd_rn(__fmul_rn(dx, dx), __fmul_rn(dy, dy)), __fmul_rn(dz, dz));
                    }
                }
                unsigned masks[NCH];
#pragma unroll
                for (int c = 0; c < NCH; ++c)
                    masks[c] = __ballot_sync(FULL, d2s[c] <= 1.0f);
#pragma unroll
                for (int c = 0; c < NCH; ++c) {
                    if (cnt < NSAMPLE) {
                        unsigned m = masks[c];
                        int rank = cnt + __popc(m & ((1u << lane) - 1u));
                        if (((m >> lane) & 1u) && rank < NSAMPLE)
                            g_ball[i * NSAMPLE + rank] = b * MK + basej + (c << 5) + lane;
                        cnt += __popc(m);
                    }
                }
            }
        }
        if (lane == 0) g_cnt[i] = cnt < NSAMPLE ? cnt : NSAMPLE;
    }
    int cntc = (i < N) ? (cnt < NSAMPLE ? cnt : NSAMPLE) : 0;

    // ---- grid barrier + scan by last-arriving block ----
    __threadfence();
    __syncthreads();
    if (tid == 0) s_last = (atomicAdd(&g_arrive, 1) == nblocks - 1) ? 1 : 0;
    __syncthreads();
    if (s_last) {
        const int PER = MAXN / 256;   // 16
        int base = tid * PER;
        int vals[PER];
        int tot = 0;
#pragma unroll
        for (int k = 0; k < PER; ++k) {
            int idx = base + k;
            int v = (idx < N) ? __ldcg(&g_cnt[idx]) : 0;
            vals[k] = v;
            tot += v;
        }
        int inc = tot;
#pragma unroll
        for (int d = 1; d < 32; d <<= 1) {
            int y = __shfl_up_sync(FULL, inc, d);
            if (lane >= d) inc += y;
        }
        if (lane == 31) wsum[wid] = inc;
        __syncthreads();
        int wpre = 0;
#pragma unroll
        for (int w = 0; w < 8; ++w)
            if (w < wid) wpre += wsum[w];
        int run = wpre + inc - tot;
#pragma unroll
        for (int k = 0; k < PER; ++k) {
            int idx = base + k;
            if (idx < N) g_off[idx] = run;
            run += vals[k];
        }
        if (tid == 255) g_total = wpre + inc;
        __syncthreads();
        if (tid == 0) {
            g_arrive = 0;              // reset for next graph replay
            __threadfence();
            atomicExch(&g_flag, 1);    // release
        }
    }
    if (tid == 0) {
        while (*((volatile int*)&g_flag) == 0) {}
    }
    __syncthreads();
    __threadfence();

    // ---- phase 2: warp-per-point scatter (no block syncs) ----
    if (cntc > 0) {
        float* srow = sbuf + wid * 1280;          // 32 rows x D (D<=40)
        float* sv   = sbuf + 10240 + wid * 40;
        int off = g_off[i];
        int bv = (lane < cntc) ? g_ball[i * NSAMPLE + lane] : 0;

        if (lane == 0) { sv[0] = px; sv[1] = py; sv[2] = pz; }
        if (lane < C) sv[3 + lane] = feat[(size_t)i * C + lane];
        if (32 + lane < C) sv[35 + lane] = feat[(size_t)i * C + 32 + lane];
        __syncwarp();

        if (lane < cntc) {
            const float* gp = new_xyz + (size_t)bv * 3;
            float* row = srow + lane * D;
            row[0] = px - gp[0];
            row[1] = py - gp[1];
            row[2] = pz - gp[2];
            for (int c = 0; c < C; ++c) row[3 + c] = sv[3 + c];
        }
        float* out_idx = out + (size_t)L * D;
        if (lane < cntc) out_idx[off + lane] = (float)bv;
        __syncwarp();

        // flat coalesced flush, float4 body
        int total = cntc * D;
        float* dst = out + (size_t)off * D;
        int nhead = (4 - (int)(((size_t)off * (size_t)D) & 3)) & 3;
        if (nhead > total) nhead = total;
        if (lane < nhead) dst[lane] = srow[lane];
        int n4 = (total - nhead) >> 2;
        float4* d4 = (float4*)(dst + nhead);
        const float* sp0 = srow + nhead;
        for (int q = lane; q < n4; q += 32) {
            const float* sp = sp0 + (q << 2);
            d4[q] = make_float4(sp[0], sp[1], sp[2], sp[3]);
        }
        int done = nhead + (n4 << 2);
        int rem2 = total - done;
        if (lane < rem2) dst[done + lane] = srow[done + lane];
    }

    // ---- reset flag for next replay ----
    if (tid == 0) {
        if (atomicAdd(&g_arrive2, 1) == nblocks - 1) {
            g_arrive2 = 0;
            atomicExch(&g_flag, 0);
        }
    }
}

// ---------------------------------------------------------------------------
// Fallback path (generic shapes): R10's 3-kernel pipeline
// ---------------------------------------------------------------------------
__global__ void query_kernel_generic(const float* __restrict__ xyz,
                                     const float* __restrict__ new_xyz,
                                     const float* __restrict__ rois,
                                     int N, int Nb, int M, int K) {
    int warp = (blockIdx.x * blockDim.x + threadIdx.x) >> 5;
    int lane = threadIdx.x & 31;
    if (warp >= N) return;
    int i = warp;
    float px = xyz[3 * i + 0], py = xyz[3 * i + 1], pz = xyz[3 * i + 2];
    int b = i / Nb;
    int MK = M * K;
    const float* roib  = rois    + (size_t)b * M * 7;
    const float* gridb = new_xyz + (size_t)b * MK * 3;
    int cnt = 0;
    int ngroups = (M + 31) >> 5;
    for (int g = 0; g < ngroups && cnt < NSAMPLE; ++g) {
        int r = (g << 5) + lane;
        bool ib = false;
        if (r < M) {
            const float* ro = roib + (size_t)r * 7;
            float dx = px - ro[0], dy = py - ro[1], dz = pz - ro[2];
            float d2b = __fadd_rn(__fadd_rn(__fmul_rn(dx, dx), __fmul_rn(dy, dy)), __fmul_rn(dz, dz));
            float r2  = __fadd_rn(__fadd_rn(__fmul_rn(ro[3], ro[3]), __fmul_rn(ro[4], ro[4])), __fmul_rn(ro[5], ro[5]));
            ib = (d2b <= r2);
        }
        unsigned rm = __ballot_sync(FULL, ib);
        while (rm && cnt < NSAMPLE) {
            int rb = __ffs(rm) - 1;
            rm &= rm - 1;
            int basej = ((g << 5) + rb) * K;
            int nchunks = (K + 31) >> 5;
            for (int c = 0; c < nchunks && cnt < NSAMPLE; ++c) {
                int jl = (c << 5) + lane;
                bool ok = false;
                if (jl < K) {
                    const float* gp = gridb + (size_t)(basej + jl) * 3;
                    float dx = px - gp[0], dy = py - gp[1], dz = pz - gp[2];
                    float d2 = __fadd_rn(__fadd_rn(__fmul_rn(dx, dx), __fmul_rn(dy, dy)), __fmul_rn(dz, dz));
                    ok = (d2 <= 1.0f);
                }
                unsigned m = __ballot_sync(FULL, ok);
                int rank = cnt + __popc(m & ((1u << lane) - 1u));
                if (ok && rank < NSAMPLE)
                    g_ball[i * NSAMPLE + rank] = b * MK + basej + jl;
                cnt += __popc(m);
            }
        }
    }
    if (lane == 0) g_cnt[i] = cnt < NSAMPLE ? cnt : NSAMPLE;
}

__global__ void scan_kernel_generic(int N) {
    __shared__ int wsum[4];
    int t = threadIdx.x, lane = t & 31, wid = t >> 5;
    const int PER = MAXN / 128;
    int base = t * PER;
    int vals[PER]; int tot = 0;
#pragma unroll
    for (int k = 0; k < PER; ++k) {
        int idx = base + k;
        int v = (idx < N) ? g_cnt[idx] : 0;
        vals[k] = v; tot += v;
    }
    int inc = tot;
#pragma unroll
    for (int d = 1; d < 32; d <<= 1) {
        int y = __shfl_up_sync(FULL, inc, d);
        if (lane >= d) inc += y;
    }
    if (lane == 31) wsum[wid] = inc;
    __syncthreads();
    int wpre = 0;
#pragma unroll
    for (int w = 0; w < 4; ++w) if (w < wid) wpre += wsum[w];
    int run = wpre + inc - tot;
#pragma unroll
    for (int k = 0; k < PER; ++k) {
        int idx = base + k;
        if (idx < N) g_off[idx] = run;
        run += vals[k];
    }
    if (t == 127) g_total = wpre + inc;
}

#define SCT_THREADS 128
#define ZBLK 1024
#define MAXD 99

__global__ void scatter_kernel_generic(const float* __restrict__ xyz,
                                       const float* __restrict__ new_xyz_flat,
                                       const float* __restrict__ feat,
                                       float* __restrict__ out_gf,
                                       float* __restrict__ out_idx,
                                       int N, int C, int L) {
    int blk = blockIdx.x;
    int t = threadIdx.x;
    int D = 3 + C;

    if (blk < N) {
        __shared__ int   sball[NSAMPLE];
        __shared__ float sval[MAXD];
        __shared__ float srow[NSAMPLE * MAXD];
        int i = blk;
        int cnt = g_cnt[i];
        if (cnt == 0) return;
        int off = g_off[i];

        if (t < cnt) sball[t] = g_ball[i * NSAMPLE + t];
        if (t < 3)   sval[t] = xyz[3 * i + t];
        if (t < C)   sval[3 + t] = feat[(size_t)i * C + t];
        __syncthreads();

        int wid = t >> 5;
        int lane = t & 31;
        float v1 = (lane      < D) ? sval[lane]      : 0.f;
        float v2 = (32 + lane < D) ? sval[32 + lane] : 0.f;
        float v3 = (64 + lane < D) ? sval[64 + lane] : 0.f;
        bool w2 = (32 + lane < D);
        bool w3 = (64 + lane < D);

        for (int s = wid; s < cnt; s += (SCT_THREADS >> 5)) {
            int idx = sball[s];
            float* row = srow + s * D;
            float v = v1;
            if (lane < 3)
                v = v1 - __ldg(&new_xyz_flat[(size_t)idx * 3 + lane]);
            if (lane < D) row[lane] = v;
            if (w2) row[32 + lane] = v2;
            if (w3) row[64 + lane] = v3;
        }
        if (t < cnt) out_idx[off + t] = (float)sball[t];
        __syncthreads();

        int total = cnt * D;
        float* dst = out_gf + (size_t)off * D;
        int nhead = (4 - (int)(((size_t)off * D) & 3)) & 3;
        if (nhead > total) nhead = total;
        if (t < nhead) dst[t] = srow[t];
        int n4 = (total - nhead) >> 2;
        float4* d4 = (float4*)(dst + nhead);
        const float* sp0 = srow + nhead;
        for (int q = t; q < n4; q += SCT_THREADS) {
            const float* sp = sp0 + (q << 2);
            d4[q] = make_float4(sp[0], sp[1], sp[2], sp[3]);
        }
        int done = nhead + (n4 << 2);
        int rem = total - done;
        if (t < rem) dst[done + t] = srow[done + t];
    } else {
        int zb = blk - N;
        int nind = g_total;
        long S = (long)nind * D;
        long E = (long)L * D;
        long gt = (long)zb * SCT_THREADS + t;
        long TOT = (long)ZBLK * SCT_THREADS;
        long S4 = (S + 3) & ~3L;
        if (S4 > E) S4 = E;
        if (gt < (S4 - S)) out_gf[S + gt] = 0.f;
        float4 z4 = make_float4(0.f, 0.f, 0.f, 0.f);
        long n4 = (E - S4) >> 2;
        float4* p4 = (float4*)(out_gf + S4);
        for (long q = gt; q < n4; q += TOT) p4[q] = z4;
        long rem = (E - S4) & 3L;
        if (gt < rem) out_gf[S4 + (n4 << 2) + gt] = 0.f;
        for (long q = nind + gt; q < L; q += TOT) out_idx[q] = 0.f;
    }
}

// ---------------------------------------------------------------------------
extern "C" void kernel_launch(void* const* d_in, const int* in_sizes, int n_in,
                              void* d_out, int out_size) {
    const float* xyz     = (const float*)d_in[0];
    const float* new_xyz = (const float*)d_in[2];
    const float* rois    = (const float*)d_in[3];
    const float* feats   = (const float*)d_in[4];

    int N  = in_sizes[0] / 3;
    int B  = in_sizes[1];
    int Nb = N / B;
    int M  = in_sizes[3] / (B * 7);
    int K  = in_sizes[2] / (B * M * 3);
    int C  = in_sizes[4] / N;
    int L  = N * NSAMPLE;
    int D  = 3 + C;
    int BM = B * M;

    int nch = (K + 31) / 32;
    int nblocks_f = (N + 7) / 8;

    bool fused = (BM <= 1024) && (N <= MAXN) && (nch >= 1) && (nch <= 8) &&
                 (D <= MAXDF) && (nblocks_f <= 576);
    if (fused) {
        switch (nch) {
        case 1: fused_kernel<1><<<nblocks_f, 256>>>(xyz, new_xyz, rois, feats, (float*)d_out, N, Nb, M, K, C, L, BM, out_size); break;
        case 2: fused_kernel<2><<<nblocks_f, 256>>>(xyz, new_xyz, rois, feats, (float*)d_out, N, Nb, M, K, C, L, BM, out_size); break;
        case 3: fused_kernel<3><<<nblocks_f, 256>>>(xyz, new_xyz, rois, feats, (float*)d_out, N, Nb, M, K, C, L, BM, out_size); break;
        case 4: fused_kernel<4><<<nblocks_f, 256>>>(xyz, new_xyz, rois, feats, (float*)d_out, N, Nb, M, K, C, L, BM, out_size); break;
        case 5: fused_kernel<5><<<nblocks_f, 256>>>(xyz, new_xyz, rois, feats, (float*)d_out, N, Nb, M, K, C, L, BM, out_size); break;
        case 6: fused_kernel<6><<<nblocks_f, 256>>>(xyz, new_xyz, rois, feats, (float*)d_out, N, Nb, M, K, C, L, BM, out_size); break;
        case 7: fused_kernel<7><<<nblocks_f, 256>>>(xyz, new_xyz, rois, feats, (float*)d_out, N, Nb, M, K, C, L, BM, out_size); break;
        default: fused_kernel<8><<<nblocks_f, 256>>>(xyz, new_xyz, rois, feats, (float*)d_out, N, Nb, M, K, C, L, BM, out_size); break;
        }
    } else {
        int nthreads = N * 32;
        int nblocks = (nthreads + 255) / 256;
        query_kernel_generic<<<nblocks, 256>>>(xyz, new_xyz, rois, N, Nb, M, K);
        scan_kernel_generic<<<1, 128>>>(N);
        scatter_kernel_generic<<<N + ZBLK, SCT_THREADS>>>(
            xyz, new_xyz, feats,
            (float*)d_out, (float*)d_out + (size_t)L * D, N, C, L);
    }
}